// round 2
// baseline (speedup 1.0000x reference)
#include <cuda_runtime.h>

#define FULL_MASK 0xFFFFFFFFu

constexpr int IN_DIM = 256;
constexpr int DEMB = 32;
constexpr int ROWS_PER_TILE = 8;
constexpr int THREADS = 256;
constexpr int WP_STRIDE = 260;   // 256 + 4 pad: (j*260+k) % 32 = (4j+k)%32 -> conflict-free LDS.128
constexpr int WS_STRIDE = 36;    // 32 + 4 pad, same property
constexpr float LN_EPS = 1e-5f;

struct Smem {
    float wp [DEMB * WP_STRIDE];      // 33280 B
    float wq [DEMB * WS_STRIDE];
    float wk [DEMB * WS_STRIDE];
    float wv [DEMB * WS_STRIDE];
    float wo1[DEMB * WS_STRIDE];
    float wo2[DEMB * WS_STRIDE];      // 5 * 4608 B
    float f  [ROWS_PER_TILE * 3 * IN_DIM];   // 24576 B
    float x  [ROWS_PER_TILE][3][DEMB];
    float pool[ROWS_PER_TILE][DEMB];
    float o1 [ROWS_PER_TILE][DEMB];
};

__device__ __forceinline__ float wsum(float v) {
    v += __shfl_xor_sync(FULL_MASK, v, 16);
    v += __shfl_xor_sync(FULL_MASK, v, 8);
    v += __shfl_xor_sync(FULL_MASK, v, 4);
    v += __shfl_xor_sync(FULL_MASK, v, 2);
    v += __shfl_xor_sync(FULL_MASK, v, 1);
    return v;
}

__device__ __forceinline__ float dot4(float4 a, float4 b) {
    return a.x * b.x + a.y * b.y + a.z * b.z + a.w * b.w;
}

__global__ __launch_bounds__(THREADS)
void msfe_kernel(const float* __restrict__ f1, const float* __restrict__ f4,
                 const float* __restrict__ fD,
                 const float* __restrict__ Wp,  const float* __restrict__ bp,
                 const float* __restrict__ ln_g, const float* __restrict__ ln_b,
                 const float* __restrict__ Wq,  const float* __restrict__ bq,
                 const float* __restrict__ Wk,  const float* __restrict__ bk,
                 const float* __restrict__ Wv,  const float* __restrict__ bv,
                 const float* __restrict__ Wo1, const float* __restrict__ bo1,
                 const float* __restrict__ Wo2, const float* __restrict__ bo2,
                 float* __restrict__ out, int B, int ntiles)
{
    extern __shared__ char smem_raw[];
    Smem* s = reinterpret_cast<Smem*>(smem_raw);

    const int tid  = threadIdx.x;
    const int lane = tid & 31;
    const int wrp  = tid >> 5;

    // ---- stage weights once per block ----
    for (int i = tid; i < DEMB * IN_DIM; i += THREADS) {
        int j = i >> 8, k = i & 255;
        s->wp[j * WP_STRIDE + k] = Wp[i];
    }
    for (int i = tid; i < DEMB * DEMB; i += THREADS) {
        int j = i >> 5, d = i & 31;
        s->wq [j * WS_STRIDE + d] = Wq [i];
        s->wk [j * WS_STRIDE + d] = Wk [i];
        s->wv [j * WS_STRIDE + d] = Wv [i];
        s->wo1[j * WS_STRIDE + d] = Wo1[i];
        s->wo2[j * WS_STRIDE + d] = Wo2[i];
    }

    // per-lane params (lane == output dim j)
    const float bp_j  = bp [lane];
    const float g_j   = ln_g[lane];
    const float b_j   = ln_b[lane];
    const float bq_j  = bq [lane];
    const float bk_j  = bk [lane];
    const float bv_j  = bv [lane];
    const float bo1_j = bo1[lane];
    const float bo2_j = bo2[lane];

    const float4* wp_row = reinterpret_cast<const float4*>(s->wp) + lane * (WP_STRIDE / 4);
    const float4* WQ4 = reinterpret_cast<const float4*>(s->wq)  + lane * (WS_STRIDE / 4);
    const float4* WK4 = reinterpret_cast<const float4*>(s->wk)  + lane * (WS_STRIDE / 4);
    const float4* WV4 = reinterpret_cast<const float4*>(s->wv)  + lane * (WS_STRIDE / 4);
    const float4* WO14 = reinterpret_cast<const float4*>(s->wo1) + lane * (WS_STRIDE / 4);
    const float4* WO24 = reinterpret_cast<const float4*>(s->wo2) + lane * (WS_STRIDE / 4);

    for (int tile = blockIdx.x; tile < ntiles; tile += gridDim.x) {
        const int row0 = tile * ROWS_PER_TILE;
        __syncthreads();   // previous tile's compute done before restaging f

        // ---- stage f tiles: 8 rows x 3 feats x 256 floats as float4 ----
        {
            float4* fdst = reinterpret_cast<float4*>(s->f);
            for (int i = tid; i < ROWS_PER_TILE * 3 * (IN_DIM / 4); i += THREADS) {
                int rf = i >> 6;         // row*3 + feat
                int c  = i & 63;         // float4 index within 256
                int r  = rf / 3;
                int ft = rf - r * 3;
                int row = row0 + r;
                float4 val = make_float4(0.f, 0.f, 0.f, 0.f);
                if (row < B) {
                    const float* src = (ft == 0) ? f1 : (ft == 1) ? f4 : fD;
                    val = reinterpret_cast<const float4*>(src + (size_t)row * IN_DIM)[c];
                }
                fdst[rf * 64 + c] = val;
            }
        }
        __syncthreads();

        const int row = row0 + wrp;
        if (row < B) {
            // ---- projection: h_s[lane] = relu(f_s . Wp[lane,:] + bp) ----
            const float4* F1 = reinterpret_cast<const float4*>(s->f + (wrp * 3 + 0) * IN_DIM);
            const float4* F4 = reinterpret_cast<const float4*>(s->f + (wrp * 3 + 1) * IN_DIM);
            const float4* FD = reinterpret_cast<const float4*>(s->f + (wrp * 3 + 2) * IN_DIM);
            float h1 = 0.f, h4 = 0.f, hD = 0.f;
            #pragma unroll 8
            for (int c = 0; c < IN_DIM / 4; c++) {
                float4 ww = wp_row[c];
                float4 a  = F1[c];
                float4 b4 = F4[c];
                float4 dd = FD[c];
                h1 += a.x * ww.x + a.y * ww.y + a.z * ww.z + a.w * ww.w;
                h4 += b4.x * ww.x + b4.y * ww.y + b4.z * ww.z + b4.w * ww.w;
                hD += dd.x * ww.x + dd.y * ww.y + dd.z * ww.z + dd.w * ww.w;
            }
            h1 = fmaxf(h1 + bp_j, 0.f);
            h4 = fmaxf(h4 + bp_j, 0.f);
            hD = fmaxf(hD + bp_j, 0.f);

            // ---- LayerNorm per feature (lane = dim) ----
            float xs[3];
            float hv[3] = {h1, h4, hD};
            #pragma unroll
            for (int ss = 0; ss < 3; ss++) {
                float v   = hv[ss];
                float mu  = wsum(v) * (1.f / 32.f);
                float dvc = v - mu;
                float var = wsum(dvc * dvc) * (1.f / 32.f);
                float inv = rsqrtf(var + LN_EPS);
                xs[ss] = g_j * dvc * inv + b_j;
            }
            s->x[wrp][0][lane] = xs[0];
            s->x[wrp][1][lane] = xs[1];
            s->x[wrp][2][lane] = xs[2];
            __syncwarp();

            // ---- QKV: q[s][lane] = X[s,:] . Wq[lane,:] + bq ----
            float qv[3], kv[3], vv[3];
            #pragma unroll
            for (int ss = 0; ss < 3; ss++) {
                const float4* XV = reinterpret_cast<const float4*>(s->x[wrp][ss]);
                float aq = bq_j, ak = bk_j, av = bv_j;
                #pragma unroll
                for (int c = 0; c < 8; c++) {
                    float4 xv = XV[c];
                    aq += dot4(xv, WQ4[c]);
                    ak += dot4(xv, WK4[c]);
                    av += dot4(xv, WV4[c]);
                }
                qv[ss] = aq; kv[ss] = ak; vv[ss] = av;
            }

            // ---- scores (3x3) via warp allreduce, softmax over t ----
            const float scale = 0.17677669529663687f;  // 1/sqrt(32)
            float att[3][3];
            #pragma unroll
            for (int ss = 0; ss < 3; ss++)
                #pragma unroll
                for (int tt = 0; tt < 3; tt++)
                    att[ss][tt] = wsum(qv[ss] * kv[tt]) * scale;

            float pooled = 0.f;
            #pragma unroll
            for (int ss = 0; ss < 3; ss++) {
                float m = fmaxf(att[ss][0], fmaxf(att[ss][1], att[ss][2]));
                float e0 = __expf(att[ss][0] - m);
                float e1 = __expf(att[ss][1] - m);
                float e2 = __expf(att[ss][2] - m);
                float rinv = 1.f / (e0 + e1 + e2);
                pooled += (e0 * vv[0] + e1 * vv[1] + e2 * vv[2]) * rinv;
            }
            pooled *= (1.f / 3.f);

            s->pool[wrp][lane] = pooled;
            __syncwarp();

            // ---- out = relu(pooled @ Wo1^T + bo1) @ Wo2^T + bo2 + pooled ----
            const float4* PV = reinterpret_cast<const float4*>(s->pool[wrp]);
            float acc1 = bo1_j;
            #pragma unroll
            for (int c = 0; c < 8; c++) acc1 += dot4(PV[c], WO14[c]);
            acc1 = fmaxf(acc1, 0.f);
            s->o1[wrp][lane] = acc1;
            __syncwarp();

            const float4* OV = reinterpret_cast<const float4*>(s->o1[wrp]);
            float acc2 = bo2_j + pooled;
            #pragma unroll
            for (int c = 0; c < 8; c++) acc2 += dot4(OV[c], WO24[c]);

            out[(size_t)row * DEMB + lane] = acc2;
        }
        __syncthreads();   // all warps done with s->f before next stage
    }
}

extern "C" void kernel_launch(void* const* d_in, const int* in_sizes, int n_in,
                              void* d_out, int out_size)
{
    const float* f1   = (const float*)d_in[0];
    const float* f4   = (const float*)d_in[1];
    const float* fD   = (const float*)d_in[2];
    const float* Wp   = (const float*)d_in[3];
    const float* bp   = (const float*)d_in[4];
    const float* ln_g = (const float*)d_in[5];
    const float* ln_b = (const float*)d_in[6];
    const float* Wq   = (const float*)d_in[7];
    const float* bq   = (const float*)d_in[8];
    const float* Wk   = (const float*)d_in[9];
    const float* bk   = (const float*)d_in[10];
    const float* Wv   = (const float*)d_in[11];
    const float* bv   = (const float*)d_in[12];
    const float* Wo1  = (const float*)d_in[13];
    const float* bo1  = (const float*)d_in[14];
    const float* Wo2  = (const float*)d_in[15];
    const float* bo2  = (const float*)d_in[16];

    const int B = in_sizes[0] / IN_DIM;
    const int ntiles = (B + ROWS_PER_TILE - 1) / ROWS_PER_TILE;
    const int smem_bytes = (int)sizeof(Smem);

    cudaFuncSetAttribute(msfe_kernel, cudaFuncAttributeMaxDynamicSharedMemorySize, smem_bytes);

    int grid = ntiles < 296 ? ntiles : 296;
    msfe_kernel<<<grid, THREADS, smem_bytes>>>(
        f1, f4, fD, Wp, bp, ln_g, ln_b, Wq, bq, Wk, bk, Wv, bv,
        Wo1, bo1, Wo2, bo2, (float*)d_out, B, ntiles);
}

// round 3
// speedup vs baseline: 1.0985x; 1.0985x over previous
#include <cuda_runtime.h>

using u64 = unsigned long long;
#define FULL_MASK 0xFFFFFFFFu

constexpr int IN_DIM  = 256;
constexpr int D       = 32;
constexpr int RPT     = 8;            // rows per tile
constexpr int NRF     = RPT * 3;      // 24 (row,feat) columns per tile
constexpr int THREADS = 256;          // 8 warps
constexpr int PART_S  = 9;            // padded stride for warp partials (9 coprime 32)
constexpr float LN_EPS = 1e-5f;

struct Smem {
    float f[NRF * IN_DIM];            // 24576 B staged input rows
    float part[NRF * D * PART_S];     // 27648 B projection partials [rf][j][w]
    float x[NRF * D];                 // 3072 B  LN outputs
    float qkv[3][NRF * D];            // 9216 B  q/k/v
    float pooled[RPT * D];            // 1024 B
    float o1[RPT * D];                // 1024 B
};

__device__ __forceinline__ void ffma2(u64& d, u64 a, u64 b) {
    asm("fma.rn.f32x2 %0, %1, %2, %0;" : "+l"(d) : "l"(a), "l"(b));
}
__device__ __forceinline__ float hsum2(u64 a, u64 b) {
    return __uint_as_float((unsigned)a) + __uint_as_float((unsigned)(a >> 32))
         + __uint_as_float((unsigned)b) + __uint_as_float((unsigned)(b >> 32));
}
__device__ __forceinline__ float wsum(float v) {
    v += __shfl_xor_sync(FULL_MASK, v, 16);
    v += __shfl_xor_sync(FULL_MASK, v, 8);
    v += __shfl_xor_sync(FULL_MASK, v, 4);
    v += __shfl_xor_sync(FULL_MASK, v, 2);
    v += __shfl_xor_sync(FULL_MASK, v, 1);
    return v;
}

__global__ __launch_bounds__(THREADS, 2)
void msfe_kernel(const float* __restrict__ f1, const float* __restrict__ f4,
                 const float* __restrict__ fD,
                 const float* __restrict__ Wp,  const float* __restrict__ bp,
                 const float* __restrict__ ln_g, const float* __restrict__ ln_b,
                 const float* __restrict__ Wq,  const float* __restrict__ bq,
                 const float* __restrict__ Wk,  const float* __restrict__ bk,
                 const float* __restrict__ Wv,  const float* __restrict__ bv,
                 const float* __restrict__ Wo1, const float* __restrict__ bo1,
                 const float* __restrict__ Wo2, const float* __restrict__ bo2,
                 float* __restrict__ out, int B, int ntiles)
{
    extern __shared__ char smem_raw[];
    Smem* s = reinterpret_cast<Smem*>(smem_raw);

    const int tid  = threadIdx.x;
    const int lane = tid & 31;          // = output dim j
    const int w    = tid >> 5;          // warp id = k-chunk (phase 1) / role (phase 2)

    // ---- register-resident weights (loaded once per launch, straight from GMEM) ----
    // Projection: thread (j=lane, kc=w) owns Wp[j][32w .. 32w+31] as 16 f32x2.
    u64 wpp[16];
    {
        const u64* src = reinterpret_cast<const u64*>(Wp + lane * IN_DIM + w * 32);
        #pragma unroll
        for (int c = 0; c < 16; c++) wpp[c] = src[c];
    }
    // Small mats: warps 0,1 -> Wq; 2,3 -> Wk; 4,5 -> Wv; 6 -> Wo1; 7 -> Wo2.
    const float* Wsel = (w < 2) ? Wq : (w < 4) ? Wk : (w < 6) ? Wv : (w == 6) ? Wo1 : Wo2;
    const float* bsel = (w < 2) ? bq : (w < 4) ? bk : (w < 6) ? bv : (w == 6) ? bo1 : bo2;
    u64 wsm[16];
    {
        const u64* src = reinterpret_cast<const u64*>(Wsel + lane * D);
        #pragma unroll
        for (int c = 0; c < 16; c++) wsm[c] = src[c];
    }
    const float bsel_j = bsel[lane];

    const float bp_j  = bp [lane];
    const float g_j   = ln_g[lane];
    const float b_j   = ln_b[lane];
    const float bo2_j = bo2[lane];

    for (int tile = blockIdx.x; tile < ntiles; tile += gridDim.x) {
        const int row0 = tile * RPT;

        // ---- stage f: RPT rows x 3 feats x 256 floats, coalesced float4 ----
        {
            float4* fdst = reinterpret_cast<float4*>(s->f);
            #pragma unroll
            for (int i = tid; i < NRF * (IN_DIM / 4); i += THREADS) {
                int rf = i >> 6;          // row*3 + feat
                int c  = i & 63;
                int r  = rf / 3;
                int ft = rf - r * 3;
                int row = row0 + r;
                float4 val = make_float4(0.f, 0.f, 0.f, 0.f);
                if (row < B) {
                    const float* src = (ft == 0) ? f1 : (ft == 1) ? f4 : fD;
                    val = reinterpret_cast<const float4*>(src + (size_t)row * IN_DIM)[c];
                }
                fdst[rf * 64 + c] = val;
            }
        }
        __syncthreads();

        // ---- projection partials: every thread does its 32-k chunk for all 24 rf ----
        #pragma unroll 4
        for (int rf = 0; rf < NRF; rf++) {
            const ulonglong2* fp =
                reinterpret_cast<const ulonglong2*>(s->f + rf * IN_DIM + w * 32);
            u64 a0 = 0ull, a1 = 0ull;
            #pragma unroll
            for (int c = 0; c < 8; c++) {
                ulonglong2 fv = fp[c];           // broadcast LDS.128 (4 floats)
                ffma2(a0, wpp[2 * c],     fv.x);
                ffma2(a1, wpp[2 * c + 1], fv.y);
            }
            s->part[(rf * D + lane) * PART_S + w] = hsum2(a0, a1);
        }
        __syncthreads();

        // ---- reduce + relu + LayerNorm: warp w handles rf in {w, w+8, w+16} ----
        #pragma unroll
        for (int idx = 0; idx < 3; idx++) {
            int rf = w + idx * 8;
            const float* pr = s->part + (rf * D + lane) * PART_S;
            float h = bp_j;
            #pragma unroll
            for (int ww = 0; ww < 8; ww++) h += pr[ww];
            h = fmaxf(h, 0.f);
            float mu  = wsum(h) * (1.f / 32.f);
            float dv  = h - mu;
            float var = wsum(dv * dv) * (1.f / 32.f);
            s->x[rf * D + lane] = g_j * dv * rsqrtf(var + LN_EPS) + b_j;
        }
        __syncthreads();

        // ---- QKV: warps 0-5 (mat = w/2, rf half = w&1), weights in regs ----
        if (w < 6) {
            const int mat  = w >> 1;
            const int rf0  = (w & 1) * (NRF / 2);
            #pragma unroll 2
            for (int rr = 0; rr < NRF / 2; rr++) {
                int rf = rf0 + rr;
                const ulonglong2* xp =
                    reinterpret_cast<const ulonglong2*>(s->x + rf * D);
                u64 a0 = 0ull, a1 = 0ull;
                #pragma unroll
                for (int c = 0; c < 8; c++) {
                    ulonglong2 xv = xp[c];
                    ffma2(a0, wsm[2 * c],     xv.x);
                    ffma2(a1, wsm[2 * c + 1], xv.y);
                }
                s->qkv[mat][rf * D + lane] = hsum2(a0, a1) + bsel_j;
            }
        }
        __syncthreads();

        // ---- attention + softmax + pool: warp w = tile row w ----
        {
            float qv[3], kv[3], vv[3];
            #pragma unroll
            for (int ss = 0; ss < 3; ss++) {
                int rf = w * 3 + ss;
                qv[ss] = s->qkv[0][rf * D + lane];
                kv[ss] = s->qkv[1][rf * D + lane];
                vv[ss] = s->qkv[2][rf * D + lane];
            }
            const float scale = 0.17677669529663687f;   // 1/sqrt(32)
            float att[3][3];
            #pragma unroll
            for (int ss = 0; ss < 3; ss++)
                #pragma unroll
                for (int tt = 0; tt < 3; tt++)
                    att[ss][tt] = wsum(qv[ss] * kv[tt]) * scale;

            float pooled = 0.f;
            #pragma unroll
            for (int ss = 0; ss < 3; ss++) {
                float m  = fmaxf(att[ss][0], fmaxf(att[ss][1], att[ss][2]));
                float e0 = __expf(att[ss][0] - m);
                float e1 = __expf(att[ss][1] - m);
                float e2 = __expf(att[ss][2] - m);
                float ri = 1.f / (e0 + e1 + e2);
                pooled += (e0 * vv[0] + e1 * vv[1] + e2 * vv[2]) * ri;
            }
            s->pooled[w * D + lane] = pooled * (1.f / 3.f);
        }
        __syncthreads();

        // ---- O1: warp 6 (Wo1 in regs) for all 8 rows ----
        if (w == 6) {
            #pragma unroll
            for (int r = 0; r < RPT; r++) {
                const ulonglong2* pv =
                    reinterpret_cast<const ulonglong2*>(s->pooled + r * D);
                u64 a0 = 0ull, a1 = 0ull;
                #pragma unroll
                for (int c = 0; c < 8; c++) {
                    ulonglong2 xv = pv[c];
                    ffma2(a0, wsm[2 * c],     xv.x);
                    ffma2(a1, wsm[2 * c + 1], xv.y);
                }
                s->o1[r * D + lane] = fmaxf(hsum2(a0, a1) + bsel_j, 0.f);
            }
        }
        __syncthreads();

        // ---- O2 + residual + store: warp 7 (Wo2 in regs) ----
        if (w == 7) {
            #pragma unroll
            for (int r = 0; r < RPT; r++) {
                int row = row0 + r;
                if (row >= B) break;
                const ulonglong2* ov =
                    reinterpret_cast<const ulonglong2*>(s->o1 + r * D);
                u64 a0 = 0ull, a1 = 0ull;
                #pragma unroll
                for (int c = 0; c < 8; c++) {
                    ulonglong2 xv = ov[c];
                    ffma2(a0, wsm[2 * c],     xv.x);
                    ffma2(a1, wsm[2 * c + 1], xv.y);
                }
                out[(size_t)row * D + lane] =
                    hsum2(a0, a1) + bo2_j + s->pooled[r * D + lane];
            }
        }
        __syncthreads();   // protect s->f / s->part before next tile
    }
}

extern "C" void kernel_launch(void* const* d_in, const int* in_sizes, int n_in,
                              void* d_out, int out_size)
{
    const float* f1   = (const float*)d_in[0];
    const float* f4   = (const float*)d_in[1];
    const float* fD   = (const float*)d_in[2];
    const float* Wp   = (const float*)d_in[3];
    const float* bp   = (const float*)d_in[4];
    const float* ln_g = (const float*)d_in[5];
    const float* ln_b = (const float*)d_in[6];
    const float* Wq   = (const float*)d_in[7];
    const float* bq   = (const float*)d_in[8];
    const float* Wk   = (const float*)d_in[9];
    const float* bk   = (const float*)d_in[10];
    const float* Wv   = (const float*)d_in[11];
    const float* bv   = (const float*)d_in[12];
    const float* Wo1  = (const float*)d_in[13];
    const float* bo1  = (const float*)d_in[14];
    const float* Wo2  = (const float*)d_in[15];
    const float* bo2  = (const float*)d_in[16];

    const int B = in_sizes[0] / IN_DIM;
    const int ntiles = (B + RPT - 1) / RPT;
    const int smem_bytes = (int)sizeof(Smem);

    cudaFuncSetAttribute(msfe_kernel, cudaFuncAttributeMaxDynamicSharedMemorySize, smem_bytes);

    int grid = ntiles < 304 ? ntiles : 304;   // 2 blocks x 152 SMs, persistent
    msfe_kernel<<<grid, THREADS, smem_bytes>>>(
        f1, f4, fD, Wp, bp, ln_g, ln_b, Wq, bq, Wk, bk, Wv, bv,
        Wo1, bo1, Wo2, bo2, (float*)d_out, B, ntiles);
}

// round 4
// speedup vs baseline: 1.1966x; 1.0893x over previous
#include <cuda_runtime.h>

using u64 = unsigned long long;
#define FULL_MASK 0xFFFFFFFFu

constexpr int IN_DIM  = 256;
constexpr int D       = 32;
constexpr int RPT     = 8;            // rows per tile (= warps per block)
constexpr int NRF     = RPT * 3;      // 24 (row,feat) units per tile
constexpr int THREADS = 256;          // 8 warps
constexpr int PART_S  = 9;            // padded stride for warp partials (coprime 32)
constexpr int WSTRIDE = 36;           // small-mat row stride (conflict-free .128)
constexpr float LN_EPS = 1e-5f;

struct Smem {
    float f[NRF * IN_DIM];            // 24576 B staged input rows
    float part[NRF * D * PART_S];     // 27648 B projection partials [rf][j][w]
    float x[NRF * D];                 // 3072 B  LN outputs
    float w5[5 * D * WSTRIDE];        // 23040 B Wq,Wk,Wv,Wo1,Wo2 (stride 36)
    float pooled[RPT][D];
    float o1[RPT][D];
};

__device__ __forceinline__ void ffma2(u64& d, u64 a, u64 b) {
    asm("fma.rn.f32x2 %0, %1, %2, %0;" : "+l"(d) : "l"(a), "l"(b));
}
__device__ __forceinline__ float hsum2(u64 a, u64 b) {
    return __uint_as_float((unsigned)a) + __uint_as_float((unsigned)(a >> 32))
         + __uint_as_float((unsigned)b) + __uint_as_float((unsigned)(b >> 32));
}
__device__ __forceinline__ float wsum(float v) {
    v += __shfl_xor_sync(FULL_MASK, v, 16);
    v += __shfl_xor_sync(FULL_MASK, v, 8);
    v += __shfl_xor_sync(FULL_MASK, v, 4);
    v += __shfl_xor_sync(FULL_MASK, v, 2);
    v += __shfl_xor_sync(FULL_MASK, v, 1);
    return v;
}

__global__ __launch_bounds__(THREADS, 2)
void msfe_kernel(const float* __restrict__ f1, const float* __restrict__ f4,
                 const float* __restrict__ fD,
                 const float* __restrict__ Wp,  const float* __restrict__ bp,
                 const float* __restrict__ ln_g, const float* __restrict__ ln_b,
                 const float* __restrict__ Wq,  const float* __restrict__ bq,
                 const float* __restrict__ Wk,  const float* __restrict__ bk,
                 const float* __restrict__ Wv,  const float* __restrict__ bv,
                 const float* __restrict__ Wo1, const float* __restrict__ bo1,
                 const float* __restrict__ Wo2, const float* __restrict__ bo2,
                 float* __restrict__ out, int B, int ntiles)
{
    extern __shared__ char smem_raw[];
    Smem* s = reinterpret_cast<Smem*>(smem_raw);

    const int tid  = threadIdx.x;
    const int lane = tid & 31;          // = output dim j
    const int w    = tid >> 5;          // warp id: k-chunk (proj) / tile row (rest)

    // ---- register-resident Wp: thread (j=lane, kc=w) owns Wp[j][32w..32w+31] ----
    u64 wpp[16];
    {
        const u64* src = reinterpret_cast<const u64*>(Wp + lane * IN_DIM + w * 32);
        #pragma unroll
        for (int c = 0; c < 16; c++) wpp[c] = src[c];
    }

    // ---- stage the 5 small mats into smem (stride 36) ----
    for (int i = tid; i < D * D; i += THREADS) {
        int j = i >> 5, d = i & 31;
        int o = j * WSTRIDE + d;
        s->w5[0 * D * WSTRIDE + o] = Wq [i];
        s->w5[1 * D * WSTRIDE + o] = Wk [i];
        s->w5[2 * D * WSTRIDE + o] = Wv [i];
        s->w5[3 * D * WSTRIDE + o] = Wo1[i];
        s->w5[4 * D * WSTRIDE + o] = Wo2[i];
    }

    // per-lane params (lane == output dim j)
    const float bp_j  = bp [lane];
    const float g_j   = ln_g[lane];
    const float b_j   = ln_b[lane];
    float bqkv[3] = { bq[lane], bk[lane], bv[lane] };
    const float bo1_j = bo1[lane];
    const float bo2_j = bo2[lane];

    // ---- per-thread constant decomposition for f staging (6 float4 / thread) ----
    const float* srcp[6];
    int rloc[6], cidx[6];
    #pragma unroll
    for (int k2 = 0; k2 < 6; k2++) {
        int i  = tid + k2 * THREADS;     // 0..1535 float4 slot
        int rf = i >> 6;                 // row*3 + feat
        cidx[k2] = i & 63;
        int r  = rf / 3;
        int ft = rf - 3 * r;
        rloc[k2] = r;
        srcp[k2] = (ft == 0) ? f1 : (ft == 1) ? f4 : fD;
    }

    float4 pf[6];
    // prologue: stage first tile
    {
        int row0 = blockIdx.x * RPT;
        #pragma unroll
        for (int k2 = 0; k2 < 6; k2++) {
            int row = row0 + rloc[k2];
            pf[k2] = (row < B)
                ? reinterpret_cast<const float4*>(srcp[k2] + (size_t)row * IN_DIM)[cidx[k2]]
                : make_float4(0.f, 0.f, 0.f, 0.f);
        }
        float4* fdst = reinterpret_cast<float4*>(s->f);
        #pragma unroll
        for (int k2 = 0; k2 < 6; k2++) fdst[tid + k2 * THREADS] = pf[k2];
    }
    __syncthreads();

    for (int tile = blockIdx.x; tile < ntiles; tile += gridDim.x) {
        const int row0 = tile * RPT;
        const int nt   = tile + gridDim.x;

        // ---- issue prefetch LDGs for next tile (latency hidden by proj) ----
        const bool have_next = (nt < ntiles);
        if (have_next) {
            int nrow0 = nt * RPT;
            #pragma unroll
            for (int k2 = 0; k2 < 6; k2++) {
                int row = nrow0 + rloc[k2];
                pf[k2] = (row < B)
                    ? reinterpret_cast<const float4*>(srcp[k2] + (size_t)row * IN_DIM)[cidx[k2]]
                    : make_float4(0.f, 0.f, 0.f, 0.f);
            }
        }

        // ---- projection partials: each thread does its 32-k chunk for all 24 rf ----
        #pragma unroll 4
        for (int rf = 0; rf < NRF; rf++) {
            const ulonglong2* fp =
                reinterpret_cast<const ulonglong2*>(s->f + rf * IN_DIM + w * 32);
            u64 a0 = 0ull, a1 = 0ull;
            #pragma unroll
            for (int c = 0; c < 8; c++) {
                ulonglong2 fv = fp[c];           // broadcast LDS.128
                ffma2(a0, wpp[2 * c],     fv.x);
                ffma2(a1, wpp[2 * c + 1], fv.y);
            }
            s->part[(rf * D + lane) * PART_S + w] = hsum2(a0, a1);
        }
        __syncthreads();

        // ---- overlap: store next tile's f  +  reduce/relu/LN ----
        if (have_next) {
            float4* fdst = reinterpret_cast<float4*>(s->f);
            #pragma unroll
            for (int k2 = 0; k2 < 6; k2++) fdst[tid + k2 * THREADS] = pf[k2];
        }
        #pragma unroll
        for (int idx = 0; idx < 3; idx++) {
            int rf = w + idx * 8;
            const float* pr = s->part + (rf * D + lane) * PART_S;
            float h = bp_j;
            #pragma unroll
            for (int ww = 0; ww < 8; ww++) h += pr[ww];
            h = fmaxf(h, 0.f);
            float mu  = wsum(h) * (1.f / 32.f);
            float dv  = h - mu;
            float var = wsum(dv * dv) * (1.f / 32.f);
            s->x[rf * D + lane] = g_j * dv * rsqrtf(var + LN_EPS) + b_j;
        }
        __syncthreads();

        // ============ per-row phase: warp w owns tile row w ============
        const int row = row0 + w;
        if (row < B) {
            // ---- QKV from smem weights (rows spread, conflict-free) ----
            float qkvr[3][3];    // [mat][ss]
            #pragma unroll
            for (int mat = 0; mat < 3; mat++) {
                const ulonglong2* wrow = reinterpret_cast<const ulonglong2*>(
                    s->w5 + mat * D * WSTRIDE + lane * WSTRIDE);
                u64 a0[3] = {0ull, 0ull, 0ull}, a1[3] = {0ull, 0ull, 0ull};
                #pragma unroll
                for (int c = 0; c < 8; c++) {
                    ulonglong2 wv = wrow[c];
                    #pragma unroll
                    for (int ss = 0; ss < 3; ss++) {
                        ulonglong2 xv = reinterpret_cast<const ulonglong2*>(
                            s->x + (w * 3 + ss) * D)[c];
                        ffma2(a0[ss], wv.x, xv.x);
                        ffma2(a1[ss], wv.y, xv.y);
                    }
                }
                #pragma unroll
                for (int ss = 0; ss < 3; ss++)
                    qkvr[mat][ss] = hsum2(a0[ss], a1[ss]) + bqkv[mat];
            }

            // ---- 3x3 scores via warp allreduce, softmax, pool ----
            const float scale = 0.17677669529663687f;   // 1/sqrt(32)
            float att[3][3];
            #pragma unroll
            for (int ss = 0; ss < 3; ss++)
                #pragma unroll
                for (int tt = 0; tt < 3; tt++)
                    att[ss][tt] = wsum(qkvr[0][ss] * qkvr[1][tt]) * scale;

            float pooled = 0.f;
            #pragma unroll
            for (int ss = 0; ss < 3; ss++) {
                float m  = fmaxf(att[ss][0], fmaxf(att[ss][1], att[ss][2]));
                float e0 = __expf(att[ss][0] - m);
                float e1 = __expf(att[ss][1] - m);
                float e2 = __expf(att[ss][2] - m);
                float ri = 1.f / (e0 + e1 + e2);
                pooled += (e0 * qkvr[2][0] + e1 * qkvr[2][1] + e2 * qkvr[2][2]) * ri;
            }
            pooled *= (1.f / 3.f);
            s->pooled[w][lane] = pooled;
            __syncwarp();

            // ---- O1 = relu(pooled @ Wo1^T + bo1) ----
            {
                const ulonglong2* pv = reinterpret_cast<const ulonglong2*>(s->pooled[w]);
                const ulonglong2* w1 = reinterpret_cast<const ulonglong2*>(
                    s->w5 + 3 * D * WSTRIDE + lane * WSTRIDE);
                u64 a0 = 0ull, a1 = 0ull;
                #pragma unroll
                for (int c = 0; c < 8; c++) {
                    ulonglong2 pvv = pv[c];
                    ulonglong2 wv  = w1[c];
                    ffma2(a0, wv.x, pvv.x);
                    ffma2(a1, wv.y, pvv.y);
                }
                s->o1[w][lane] = fmaxf(hsum2(a0, a1) + bo1_j, 0.f);
            }
            __syncwarp();

            // ---- out = O1 @ Wo2^T + bo2 + pooled ----
            {
                const ulonglong2* ov = reinterpret_cast<const ulonglong2*>(s->o1[w]);
                const ulonglong2* w2 = reinterpret_cast<const ulonglong2*>(
                    s->w5 + 4 * D * WSTRIDE + lane * WSTRIDE);
                u64 a0 = 0ull, a1 = 0ull;
                #pragma unroll
                for (int c = 0; c < 8; c++) {
                    ulonglong2 ovv = ov[c];
                    ulonglong2 wv  = w2[c];
                    ffma2(a0, wv.x, ovv.x);
                    ffma2(a1, wv.y, ovv.y);
                }
                out[(size_t)row * D + lane] = hsum2(a0, a1) + bo2_j + pooled;
            }
        }
        __syncthreads();   // protect s->x / s->f before next tile's writes
    }
}

extern "C" void kernel_launch(void* const* d_in, const int* in_sizes, int n_in,
                              void* d_out, int out_size)
{
    const float* f1   = (const float*)d_in[0];
    const float* f4   = (const float*)d_in[1];
    const float* fD   = (const float*)d_in[2];
    const float* Wp   = (const float*)d_in[3];
    const float* bp   = (const float*)d_in[4];
    const float* ln_g = (const float*)d_in[5];
    const float* ln_b = (const float*)d_in[6];
    const float* Wq   = (const float*)d_in[7];
    const float* bq   = (const float*)d_in[8];
    const float* Wk   = (const float*)d_in[9];
    const float* bk   = (const float*)d_in[10];
    const float* Wv   = (const float*)d_in[11];
    const float* bv   = (const float*)d_in[12];
    const float* Wo1  = (const float*)d_in[13];
    const float* bo1  = (const float*)d_in[14];
    const float* Wo2  = (const float*)d_in[15];
    const float* bo2  = (const float*)d_in[16];

    const int B = in_sizes[0] / IN_DIM;
    const int ntiles = (B + RPT - 1) / RPT;
    const int smem_bytes = (int)sizeof(Smem);

    cudaFuncSetAttribute(msfe_kernel, cudaFuncAttributeMaxDynamicSharedMemorySize, smem_bytes);

    int grid = ntiles < 304 ? ntiles : 304;   // 2 blocks x 152 SMs, persistent
    msfe_kernel<<<grid, THREADS, smem_bytes>>>(
        f1, f4, fD, Wp, bp, ln_g, ln_b, Wq, bq, Wk, bk, Wv, bv,
        Wo1, bo1, Wo2, bo2, (float*)d_out, B, ntiles);
}